// round 4
// baseline (speedup 1.0000x reference)
#include <cuda_runtime.h>
#include <cstdint>

// OcrEmbedding: out[b,t,:] = sum_{s=0..3, id!=0} table[id[b,t,s], :]
// B=32, T=512, S=4, D=256, V=50000.
// d_in[0] = subtoken_ids (int32, B*T*S), d_in[1] = table (float32, V*D)
// Output: float32, B*T*D.
//
// Strategy: TMA bulk-copy gather (cp.async.bulk, UBLKCP) to bypass the
// per-SM LDG/L1tex outstanding-request wall. Each CTA handles R=8 token
// rows; one elected thread issues 32 independent 1KB bulk copies
// (global row -> smem) tracked by a single mbarrier with transaction
// accounting. Sum stage masks id==0 rows.

#define BT      (32 * 512)   // 16384 token rows
#define D4      64           // float4 chunks per 256-float row
#define R       8            // token rows per CTA
#define THREADS 256
#define ROW_BYTES 1024       // 256 floats

__device__ __forceinline__ uint32_t smem_u32(const void* p) {
    uint32_t a;
    asm("{ .reg .u64 t; cvta.to.shared.u64 t, %1; cvt.u32.u64 %0, t; }"
        : "=r"(a) : "l"(p));
    return a;
}

__global__ __launch_bounds__(THREADS) void ocr_embed_tma_kernel(
    const int* __restrict__ ids,          // [BT*4]
    const float* __restrict__ table,      // [V*256]
    float4* __restrict__ out)             // [BT, D4]
{
    // 32 KB gather buffer + mbarrier
    __shared__ __align__(128) float4 buf[R * 4 * D4];
    __shared__ __align__(8) uint64_t mbar;

    const int tid  = threadIdx.x;
    const int row0 = blockIdx.x * R;

    uint32_t mbar_a = smem_u32(&mbar);

    if (tid == 0) {
        asm volatile("mbarrier.init.shared.b64 [%0], 1;" :: "r"(mbar_a) : "memory");
    }
    __syncthreads();

    if (tid == 0) {
        // Load the 32 ids (contiguous 128B), count expected bytes, issue copies.
        int idv[R * 4];
        uint32_t tx = 0;
        #pragma unroll
        for (int c = 0; c < R * 4; c++) {
            idv[c] = __ldg(&ids[row0 * 4 + c]);
            tx += (idv[c] != 0) ? ROW_BYTES : 0u;
        }
        asm volatile("mbarrier.arrive.expect_tx.shared.b64 _, [%0], %1;"
                     :: "r"(mbar_a), "r"(tx) : "memory");
        #pragma unroll
        for (int c = 0; c < R * 4; c++) {
            if (idv[c] != 0) {
                const float* src = table + (size_t)idv[c] * 256;
                uint32_t dst = smem_u32(&buf[c * D4]);
                asm volatile(
                    "cp.async.bulk.shared::cta.global.mbarrier::complete_tx::bytes "
                    "[%0], [%1], %2, [%3];"
                    :: "r"(dst), "l"(src), "n"(ROW_BYTES), "r"(mbar_a) : "memory");
            }
        }
    }

    // All threads wait for gather completion (phase 0).
    {
        uint32_t done;
        asm volatile(
            "{\n\t"
            ".reg .pred p;\n\t"
            "mbarrier.try_wait.parity.acquire.cta.shared::cta.b64 p, [%1], 0;\n\t"
            "selp.b32 %0, 1, 0, p;\n\t"
            "}" : "=r"(done) : "r"(mbar_a) : "memory");
        if (!done) {
            asm volatile(
                "{\n\t"
                ".reg .pred P1;\n\t"
                "WL_%=:\n\t"
                "mbarrier.try_wait.parity.acquire.cta.shared::cta.b64 P1, [%0], 0, 0x989680;\n\t"
                "@P1 bra.uni WD_%=;\n\t"
                "bra.uni WL_%=;\n\t"
                "WD_%=:\n\t"
                "}" :: "r"(mbar_a) : "memory");
        }
    }

    // Sum stage: R*64 = 512 output chunks, 2 per thread. Mask id==0 rows.
    #pragma unroll
    for (int j = 0; j < 2; j++) {
        int o = tid + THREADS * j;
        int r = o >> 6;
        int q = o & 63;

        int4 id = __ldg((const int4*)(ids + (row0 + r) * 4));  // L1-hot broadcast

        const float4* p = &buf[(r * 4) * D4 + q];
        float4 s = make_float4(0.f, 0.f, 0.f, 0.f);
        if (id.x != 0) { float4 v = p[0];       s.x += v.x; s.y += v.y; s.z += v.z; s.w += v.w; }
        if (id.y != 0) { float4 v = p[D4];      s.x += v.x; s.y += v.y; s.z += v.z; s.w += v.w; }
        if (id.z != 0) { float4 v = p[2 * D4];  s.x += v.x; s.y += v.y; s.z += v.z; s.w += v.w; }
        if (id.w != 0) { float4 v = p[3 * D4];  s.x += v.x; s.y += v.y; s.z += v.z; s.w += v.w; }

        out[(size_t)(row0 + r) * D4 + q] = s;
    }
}

extern "C" void kernel_launch(void* const* d_in, const int* in_sizes, int n_in,
                              void* d_out, int out_size)
{
    const int*   ids   = (const int*)d_in[0];
    const float* table = (const float*)d_in[1];
    float4*      out   = (float4*)d_out;

    const int blocks = BT / R;   // 2048
    ocr_embed_tma_kernel<<<blocks, THREADS>>>(ids, table, out);
}

// round 5
// speedup vs baseline: 1.1604x; 1.1604x over previous
#include <cuda_runtime.h>
#include <cstdint>

// OcrEmbedding: out[b,t,:] = sum_{s=0..3, id!=0} table[id[b,t,s], :]
// B=32, T=512, S=4, D=256, V=50000.
// d_in[0] = subtoken_ids (int32, B*T*S), d_in[1] = table (float32, V*D)
// Output: float32, B*T*D.
//
// Hybrid gather: the per-SM LDG/L1tex in-flight cap (~64 lines) limits the
// pure-LDG kernel to ~7.9 TB/s warm. TMA bulk copies use a separate queue.
// Each CTA: 16 token rows = 12 via LDG (R1 scheme) + 4 via TMA bulk->smem,
// issued by 16 threads in parallel (one 1KB copy each, per-thread expect_tx).

#define BT      (32 * 512)   // 16384 token rows
#define D4      64           // float4 chunks per 256-float row
#define R_ALL   16           // rows per CTA
#define R_LDG   12           // rows via LDG path
#define R_TMA   4            // rows via TMA path
#define THREADS 256
#define ROW_BYTES 1024

__device__ __forceinline__ uint32_t smem_u32(const void* p) {
    uint32_t a;
    asm("{ .reg .u64 t; cvta.to.shared.u64 t, %1; cvt.u32.u64 %0, t; }"
        : "=r"(a) : "l"(p));
    return a;
}

__global__ __launch_bounds__(THREADS) void ocr_embed_hybrid_kernel(
    const int* __restrict__ ids,          // [BT*4]
    const float* __restrict__ table,      // [V*256]
    float4* __restrict__ out)             // [BT, D4]
{
    __shared__ __align__(128) float4 buf[R_TMA * 4 * D4];   // 16 KB
    __shared__ __align__(8) uint64_t mbar;

    const int tid  = threadIdx.x;
    const int row0 = blockIdx.x * R_ALL;

    const uint32_t mbar_a = smem_u32(&mbar);

    if (tid == 0) {
        // 16 arrivals: one per issuing thread (each carries its expect_tx).
        asm volatile("mbarrier.init.shared.b64 [%0], 16;" :: "r"(mbar_a) : "memory");
    }
    __syncthreads();

    // ---- TMA issue: threads 0..15, one 1KB bulk copy each ----
    if (tid < R_TMA * 4) {
        int r  = R_LDG + (tid >> 2);          // rows 12..15
        int s  = tid & 3;
        int id = __ldg(&ids[(row0 + r) * 4 + s]);
        uint32_t tx = (id != 0) ? ROW_BYTES : 0u;
        asm volatile("mbarrier.arrive.expect_tx.shared.b64 _, [%0], %1;"
                     :: "r"(mbar_a), "r"(tx) : "memory");
        if (id != 0) {
            const float* src = table + (size_t)id * 256;
            uint32_t dst = smem_u32(&buf[tid * D4]);
            asm volatile(
                "cp.async.bulk.shared::cta.global.mbarrier::complete_tx::bytes "
                "[%0], [%1], %2, [%3];"
                :: "r"(dst), "l"(src), "n"(ROW_BYTES), "r"(mbar_a) : "memory");
        }
    }

    // ---- LDG path: 12 rows, 64 threads/row, 3 passes (R1 scheme) ----
    {
        const int q    = tid & 63;
        const int rsub = tid >> 6;            // 0..3
        #pragma unroll
        for (int p = 0; p < 3; p++) {
            int row = row0 + p * 4 + rsub;
            int4 id = __ldg((const int4*)(ids + row * 4));

            float4 acc = make_float4(0.f, 0.f, 0.f, 0.f);
            if (id.x != 0) {
                float4 v = __ldg((const float4*)(table + (size_t)id.x * 256) + q);
                acc.x += v.x; acc.y += v.y; acc.z += v.z; acc.w += v.w;
            }
            if (id.y != 0) {
                float4 v = __ldg((const float4*)(table + (size_t)id.y * 256) + q);
                acc.x += v.x; acc.y += v.y; acc.z += v.z; acc.w += v.w;
            }
            if (id.z != 0) {
                float4 v = __ldg((const float4*)(table + (size_t)id.z * 256) + q);
                acc.x += v.x; acc.y += v.y; acc.z += v.z; acc.w += v.w;
            }
            if (id.w != 0) {
                float4 v = __ldg((const float4*)(table + (size_t)id.w * 256) + q);
                acc.x += v.x; acc.y += v.y; acc.z += v.z; acc.w += v.w;
            }
            __stcs(&out[(size_t)row * D4 + q], acc);   // evict-first: out not re-read
        }
    }

    // ---- Wait for TMA completion (phase 0) ----
    {
        uint32_t done;
        asm volatile(
            "{\n\t"
            ".reg .pred p;\n\t"
            "mbarrier.try_wait.parity.acquire.cta.shared::cta.b64 p, [%1], 0;\n\t"
            "selp.b32 %0, 1, 0, p;\n\t"
            "}" : "=r"(done) : "r"(mbar_a) : "memory");
        if (!done) {
            asm volatile(
                "{\n\t"
                ".reg .pred P1;\n\t"
                "WL_%=:\n\t"
                "mbarrier.try_wait.parity.acquire.cta.shared::cta.b64 P1, [%0], 0, 0x989680;\n\t"
                "@P1 bra.uni WD_%=;\n\t"
                "bra.uni WL_%=;\n\t"
                "WD_%=:\n\t"
                "}" :: "r"(mbar_a) : "memory");
        }
    }

    // ---- Sum TMA rows: 4 rows * 64 chunks = 256 chunks, one per thread ----
    {
        int rloc = tid >> 6;                  // 0..3
        int q    = tid & 63;
        int row  = row0 + R_LDG + rloc;
        int4 id  = __ldg((const int4*)(ids + row * 4));

        const float4* p = &buf[(rloc * 4) * D4 + q];
        float4 s = make_float4(0.f, 0.f, 0.f, 0.f);
        if (id.x != 0) { float4 v = p[0];      s.x += v.x; s.y += v.y; s.z += v.z; s.w += v.w; }
        if (id.y != 0) { float4 v = p[D4];     s.x += v.x; s.y += v.y; s.z += v.z; s.w += v.w; }
        if (id.z != 0) { float4 v = p[2 * D4]; s.x += v.x; s.y += v.y; s.z += v.z; s.w += v.w; }
        if (id.w != 0) { float4 v = p[3 * D4]; s.x += v.x; s.y += v.y; s.z += v.z; s.w += v.w; }

        __stcs(&out[(size_t)row * D4 + q], s);
    }
}

extern "C" void kernel_launch(void* const* d_in, const int* in_sizes, int n_in,
                              void* d_out, int out_size)
{
    const int*   ids   = (const int*)d_in[0];
    const float* table = (const float*)d_in[1];
    float4*      out   = (float4*)d_out;

    const int blocks = BT / R_ALL;   // 1024
    ocr_embed_hybrid_kernel<<<blocks, THREADS>>>(ids, table, out);
}